// round 3
// baseline (speedup 1.0000x reference)
#include <cuda_runtime.h>
#include <cstdint>

#define D      64
#define NNODE  16384
#define NEDGE  32768
#define NGRAPH 256
#define NTORS  3072      // NGRAPH * 12

// ---------------- device scratch (static allocations only) ----------------
__device__ float g_ew[(size_t)NEDGE * 4096];   // 512 MB edge-conditioned weights [E, d*d]
__device__ float g_h1[(size_t)NEDGE * D];      // edge hidden after e1
__device__ float g_nf[(size_t)NNODE * D];      // node features (out == h)
__device__ float g_agg[(size_t)NNODE * D];     // scatter-sum buffer
__device__ float g_deg[NNODE];                 // in-degree
__device__ float g_hx[NGRAPH * D];             // memory-LSTM hidden

__device__ __forceinline__ float sigf(float x) { return 1.0f / (1.0f + expf(-x)); }

// ---------------- lin0 + relu ----------------
__global__ void k_lin0(const float* __restrict__ x, const float* __restrict__ w,
                       const float* __restrict__ b) {
    int idx = blockIdx.x * blockDim.x + threadIdx.x;
    if (idx >= NNODE * D) return;
    int n = idx >> 6, j = idx & 63;
    float v = b[j];
    v = fmaf(x[n * 3 + 0], w[j * 3 + 0], v);
    v = fmaf(x[n * 3 + 1], w[j * 3 + 1], v);
    v = fmaf(x[n * 3 + 2], w[j * 3 + 2], v);
    g_nf[idx] = fmaxf(v, 0.0f);
}

// ---------------- edge hidden: relu(edge_attr @ e1_w^T + b) ----------------
__global__ void k_eh(const float* __restrict__ ea, const float* __restrict__ w,
                     const float* __restrict__ b) {
    int idx = blockIdx.x * blockDim.x + threadIdx.x;
    if (idx >= NEDGE * D) return;
    int e = idx >> 6, j = idx & 63;
    float acc = b[j];
#pragma unroll
    for (int c = 0; c < 6; c++) acc = fmaf(ea[e * 6 + c], w[j * 6 + c], acc);
    g_h1[idx] = fmaxf(acc, 0.0f);
}

// ---------------- degree ----------------
__global__ void k_zero_deg() {
    int i = blockIdx.x * blockDim.x + threadIdx.x;
    if (i < NNODE) g_deg[i] = 0.0f;
}
__global__ void k_deg(const int* __restrict__ ei) {
    int e = blockIdx.x * blockDim.x + threadIdx.x;
    if (e < NEDGE) atomicAdd(&g_deg[ei[NEDGE + e]], 1.0f);
}
__global__ void k_zero_agg() {
    int i = blockIdx.x * blockDim.x + threadIdx.x;
    if (i < NNODE * D) g_agg[i] = 0.0f;
}

// ---------------- ew GEMM: [E,64] @ e2_w^T[64,4096] + e2_b -> g_ew ----------------
// BM=64, BN=64, K=64 single pass; 256 threads, 4x4 register tile per thread.
__global__ void k_gemm(const float* __restrict__ B, const float* __restrict__ bias) {
    __shared__ float As[64][68];   // [m][k] (padded, coalesced fill, broadcast reads)
    __shared__ float Bs[64][68];   // [k][nn] transposed
    int tid = threadIdx.x;
    int m0 = blockIdx.x * 64, n0 = blockIdx.y * 64;
#pragma unroll
    for (int i = 0; i < 4; i++) {
        int l = tid + i * 256;
        int m = l >> 4, k4 = (l & 15) << 2;
        float4 v = *(const float4*)(g_h1 + (size_t)(m0 + m) * 64 + k4);
        *(float4*)(&As[m][k4]) = v;
    }
#pragma unroll
    for (int i = 0; i < 4; i++) {
        int l = tid + i * 256;
        int nn = l >> 4, k4 = (l & 15) << 2;
        float4 v = *(const float4*)(B + (size_t)(n0 + nn) * 64 + k4);
        Bs[k4 + 0][nn] = v.x; Bs[k4 + 1][nn] = v.y;
        Bs[k4 + 2][nn] = v.z; Bs[k4 + 3][nn] = v.w;
    }
    __syncthreads();
    int mb = (tid >> 4) * 4, nb = (tid & 15) * 4;
    float acc[4][4] = {};
#pragma unroll
    for (int k = 0; k < 64; k++) {
        float a0 = As[mb + 0][k], a1 = As[mb + 1][k], a2 = As[mb + 2][k], a3 = As[mb + 3][k];
        float4 bv = *(const float4*)(&Bs[k][nb]);
        acc[0][0] = fmaf(a0, bv.x, acc[0][0]); acc[0][1] = fmaf(a0, bv.y, acc[0][1]);
        acc[0][2] = fmaf(a0, bv.z, acc[0][2]); acc[0][3] = fmaf(a0, bv.w, acc[0][3]);
        acc[1][0] = fmaf(a1, bv.x, acc[1][0]); acc[1][1] = fmaf(a1, bv.y, acc[1][1]);
        acc[1][2] = fmaf(a1, bv.z, acc[1][2]); acc[1][3] = fmaf(a1, bv.w, acc[1][3]);
        acc[2][0] = fmaf(a2, bv.x, acc[2][0]); acc[2][1] = fmaf(a2, bv.y, acc[2][1]);
        acc[2][2] = fmaf(a2, bv.z, acc[2][2]); acc[2][3] = fmaf(a2, bv.w, acc[2][3]);
        acc[3][0] = fmaf(a3, bv.x, acc[3][0]); acc[3][1] = fmaf(a3, bv.y, acc[3][1]);
        acc[3][2] = fmaf(a3, bv.z, acc[3][2]); acc[3][3] = fmaf(a3, bv.w, acc[3][3]);
    }
    float4 bb = *(const float4*)(bias + n0 + nb);
#pragma unroll
    for (int i = 0; i < 4; i++) {
        float4 o;
        o.x = acc[i][0] + bb.x; o.y = acc[i][1] + bb.y;
        o.z = acc[i][2] + bb.z; o.w = acc[i][3] + bb.w;
        *(float4*)(g_ew + (size_t)(m0 + mb + i) * 4096 + n0 + nb) = o;
    }
}

// ---------------- message + scatter-add: msg_e = nf[src] @ ew_e ----------------
__global__ void k_msg(const int* __restrict__ ei) {
    int le = threadIdx.x >> 6;
    int o  = threadIdx.x & 63;
    int e  = blockIdx.x * 4 + le;
    __shared__ float s[4][64];
    int src = ei[e];
    s[le][o] = g_nf[(size_t)src * 64 + o];
    __syncthreads();
    const float* w = g_ew + (size_t)e * 4096 + o;
    float acc = 0.0f;
#pragma unroll 16
    for (int i = 0; i < 64; i++) acc = fmaf(s[le][i], w[(size_t)i * 64], acc);
    atomicAdd(&g_agg[(size_t)ei[NEDGE + e] * 64 + o], acc);
}

// ---------------- conv-root + relu + GRU (fused, in-place on g_nf) ----------------
__global__ void k_gru(const float* __restrict__ root_w, const float* __restrict__ conv_b,
                      const float* __restrict__ wih, const float* __restrict__ whh,
                      const float* __restrict__ bih, const float* __restrict__ bhh) {
    int li = threadIdx.x >> 6;
    int j  = threadIdx.x & 63;
    int node = blockIdx.x * 4 + li;
    __shared__ float sh[4][64];
    __shared__ float sm[4][64];
    float hj = g_nf[(size_t)node * 64 + j];
    sh[li][j] = hj;
    __syncthreads();
    // m = relu(agg/deg + h @ root_w + conv_b)
    float acc = g_agg[(size_t)node * 64 + j] / fmaxf(g_deg[node], 1.0f);
#pragma unroll 8
    for (int i = 0; i < 64; i++) acc = fmaf(sh[li][i], root_w[i * 64 + j], acc);
    float m = fmaxf(acc + conv_b[j], 0.0f);
    sm[li][j] = m;
    __syncthreads();
    float gi0 = bih[j], gi1 = bih[64 + j], gi2 = bih[128 + j];
    float gh0 = bhh[j], gh1 = bhh[64 + j], gh2 = bhh[128 + j];
    const float* wi0 = wih + (size_t)j * 64;
    const float* wi1 = wih + (size_t)(64 + j) * 64;
    const float* wi2 = wih + (size_t)(128 + j) * 64;
    const float* wh0 = whh + (size_t)j * 64;
    const float* wh1 = whh + (size_t)(64 + j) * 64;
    const float* wh2 = whh + (size_t)(128 + j) * 64;
#pragma unroll 8
    for (int c = 0; c < 64; c++) {
        float mc = sm[li][c], hc = sh[li][c];
        gi0 = fmaf(mc, wi0[c], gi0);
        gi1 = fmaf(mc, wi1[c], gi1);
        gi2 = fmaf(mc, wi2[c], gi2);
        gh0 = fmaf(hc, wh0[c], gh0);
        gh1 = fmaf(hc, wh1[c], gh1);
        gh2 = fmaf(hc, wh2[c], gh2);
    }
    float r  = sigf(gi0 + gh0);
    float z  = sigf(gi1 + gh1);
    float nn = tanhf(gi2 + r * gh2);
    g_nf[(size_t)node * 64 + j] = (1.0f - z) * nn + z * hj;
}

// ---------------- Set2Set (6 steps) + memory LSTM, one block per graph ----------------
__global__ void k_s2s(const float* __restrict__ wih, const float* __restrict__ whh,
                      const float* __restrict__ bih, const float* __restrict__ bhh,
                      const float* __restrict__ mwih, const float* __restrict__ mwhh,
                      const float* __restrict__ mbih, const float* __restrict__ mbhh,
                      float* d_hx_out, float* d_cx_out, int write_out) {
    int g = blockIdx.x, t = threadIdx.x;   // 128 threads
    __shared__ float so[64][65];
    __shared__ float hs[64], cs[64], q[128], gb[256], ab[64], red[64];
    for (int idx = t; idx < 4096; idx += 128)
        so[idx >> 6][idx & 63] = g_nf[(size_t)g * 4096 + idx];
    if (t < 64) { hs[t] = 0.0f; cs[t] = 0.0f; }
    q[t] = 0.0f;
    __syncthreads();
    for (int step = 0; step < 6; step++) {
        // LSTM gates: each thread computes rows t and t+128 of g [256]
#pragma unroll
        for (int h2 = 0; h2 < 2; h2++) {
            int r = t + h2 * 128;
            float acc = bih[r] + bhh[r];
            const float* wr = wih + (size_t)r * 128;
#pragma unroll 8
            for (int c = 0; c < 128; c++) acc = fmaf(q[c], wr[c], acc);
            const float* vr = whh + (size_t)r * 64;
#pragma unroll 8
            for (int c = 0; c < 64; c++) acc = fmaf(hs[c], vr[c], acc);
            gb[r] = acc;
        }
        __syncthreads();
        if (t < 64) {
            float c = sigf(gb[64 + t]) * cs[t] + sigf(gb[t]) * tanhf(gb[128 + t]);
            cs[t] = c;
            hs[t] = sigf(gb[192 + t]) * tanhf(c);
        }
        __syncthreads();
        // attention logits
        if (t < 64) {
            float acc = 0.0f;
#pragma unroll 8
            for (int dd = 0; dd < 64; dd++) acc = fmaf(so[t][dd], hs[dd], acc);
            ab[t] = acc; red[t] = acc;
        }
        __syncthreads();
        for (int s = 32; s > 0; s >>= 1) {
            if (t < s) red[t] = fmaxf(red[t], red[t + s]);
            __syncthreads();
        }
        float emax = red[0];
        __syncthreads();
        if (t < 64) { float a = expf(ab[t] - emax); ab[t] = a; red[t] = a; }
        __syncthreads();
        for (int s = 32; s > 0; s >>= 1) {
            if (t < s) red[t] += red[t + s];
            __syncthreads();
        }
        float asum = red[0];
        __syncthreads();
        if (t < 64) {
            float acc = 0.0f;
#pragma unroll 8
            for (int n2 = 0; n2 < 64; n2++) acc = fmaf(ab[n2], so[n2][t], acc);
            q[t] = hs[t];
            q[64 + t] = acc / asum;
        }
        __syncthreads();
    }
    // memory LSTM from zero state
#pragma unroll
    for (int h2 = 0; h2 < 2; h2++) {
        int r = t + h2 * 128;
        float acc = mbih[r] + mbhh[r];
        const float* wr = mwih + (size_t)r * 128;
#pragma unroll 8
        for (int c = 0; c < 128; c++) acc = fmaf(q[c], wr[c], acc);
        gb[r] = acc;
    }
    __syncthreads();
    if (t < 64) {
        float c  = sigf(gb[t]) * tanhf(gb[128 + t]);   // f*0 + i*tanh(g)
        float hx = sigf(gb[192 + t]) * tanhf(c);
        g_hx[g * 64 + t] = hx;
        if (write_out) { d_hx_out[g * 64 + t] = hx; d_cx_out[g * 64 + t] = c; }
    }
}

// ---------------- head: faithful view(4,-1,d)+transpose(2,1,0) feat -> lin1 -> lin2 ----------------
__global__ void k_final(const int* __restrict__ nonring, const int* __restrict__ nrbidx,
                        const float* __restrict__ w1, const float* __restrict__ b1,
                        const float* __restrict__ w2, const float* __restrict__ b2,
                        float* __restrict__ outp) {
    int r = blockIdx.x, t = threadIdx.x;   // 128 threads
    __shared__ float feat[320];
    __shared__ float o1[64];
    for (int c = t; c < 320; c += 128) {
        int flat = r * 320 + c;
        int i0 = flat / 15360;            // dim index (0..63)
        int rem = flat - i0 * 15360;
        int i1 = rem / 5;                 // torsion index
        int i2 = rem - i1 * 5;            // which of [lstm, n0..n3]
        float v;
        if (i2 == 0) v = g_hx[nrbidx[i1] * 64 + i0];
        else {
            int node = nonring[(i2 - 1) * NTORS + i1];
            v = g_nf[(size_t)node * 64 + i0];
        }
        feat[c] = v;
    }
    __syncthreads();
    if (t < 64) {
        float acc = b1[t];
        const float* wr = w1 + (size_t)t * 320;
#pragma unroll 8
        for (int c = 0; c < 320; c++) acc = fmaf(feat[c], wr[c], acc);
        o1[t] = fmaxf(acc, 0.0f);
    }
    __syncthreads();
    if (t < 6) {
        float acc = b2[t];
        const float* wr = w2 + (size_t)t * 64;
#pragma unroll
        for (int c = 0; c < 64; c++) acc = fmaf(o1[c], wr[c], acc);
        outp[r * 6 + t] = acc;
    }
}

// ---------------- launch ----------------
extern "C" void kernel_launch(void* const* d_in, const int* in_sizes, int n_in,
                              void* d_out, int out_size) {
    const float* x       = (const float*)d_in[0];
    const float* ea      = (const float*)d_in[1];
    const int*   ei      = (const int*)d_in[2];
    // d_in[3] = batch (contiguous blocks of 64, handled implicitly)
    const int*   nonring = (const int*)d_in[4];
    const int*   nrbidx  = (const int*)d_in[5];
    int base = n_in - 24;   // 24 trailing weight tensors, robust to scalar inputs
    const float* lin0_w  = (const float*)d_in[base + 0];
    const float* lin0_b  = (const float*)d_in[base + 1];
    const float* e1_w    = (const float*)d_in[base + 2];
    const float* e1_b    = (const float*)d_in[base + 3];
    const float* e2_w    = (const float*)d_in[base + 4];
    const float* e2_b    = (const float*)d_in[base + 5];
    const float* root_w  = (const float*)d_in[base + 6];
    const float* conv_b  = (const float*)d_in[base + 7];
    const float* gru_wih = (const float*)d_in[base + 8];
    const float* gru_whh = (const float*)d_in[base + 9];
    const float* gru_bih = (const float*)d_in[base + 10];
    const float* gru_bhh = (const float*)d_in[base + 11];
    const float* s2s_wih = (const float*)d_in[base + 12];
    const float* s2s_whh = (const float*)d_in[base + 13];
    const float* s2s_bih = (const float*)d_in[base + 14];
    const float* s2s_bhh = (const float*)d_in[base + 15];
    const float* mem_wih = (const float*)d_in[base + 16];
    const float* mem_whh = (const float*)d_in[base + 17];
    const float* mem_bih = (const float*)d_in[base + 18];
    const float* mem_bhh = (const float*)d_in[base + 19];
    const float* lin1_w  = (const float*)d_in[base + 20];
    const float* lin1_b  = (const float*)d_in[base + 21];
    const float* lin2_w  = (const float*)d_in[base + 22];
    const float* lin2_b  = (const float*)d_in[base + 23];
    float* outp = (float*)d_out;

    k_lin0<<<(NNODE * D) / 256, 256>>>(x, lin0_w, lin0_b);
    k_eh<<<(NEDGE * D) / 256, 256>>>(ea, e1_w, e1_b);
    k_zero_deg<<<NNODE / 256, 256>>>();
    k_deg<<<NEDGE / 256, 256>>>(ei);
    k_gemm<<<dim3(NEDGE / 64, 4096 / 64), 256>>>(e2_w, e2_b);

    for (int it = 0; it < 6; it++) {
        k_zero_agg<<<(NNODE * D) / 256, 256>>>();
        k_msg<<<NEDGE / 4, 256>>>(ei);
        k_gru<<<NNODE / 4, 256>>>(root_w, conv_b, gru_wih, gru_whh, gru_bih, gru_bhh);
    }

    int wout = (out_size >= 51200) ? 1 : 0;
    k_s2s<<<NGRAPH, 128>>>(s2s_wih, s2s_whh, s2s_bih, s2s_bhh,
                           mem_wih, mem_whh, mem_bih, mem_bhh,
                           outp + 18432, outp + 18432 + 16384, wout);
    k_final<<<NTORS, 128>>>(nonring, nrbidx, lin1_w, lin1_b, lin2_w, lin2_b, outp);
}

// round 4
// speedup vs baseline: 8.2012x; 8.2012x over previous
#include <cuda_runtime.h>
#include <cuda_fp16.h>
#include <cstdint>

#define D      64
#define NNODE  16384
#define NEDGE  32768
#define NGRAPH 256
#define NTORS  3072      // NGRAPH * 12

// ---------------- device scratch (static allocations only) ----------------
__device__ __half g_ewh[(size_t)NEDGE * 4096];  // 256 MB edge weights, fp16 [E][i][o]
__device__ float g_h1[(size_t)NEDGE * D];       // edge hidden after e1
__device__ float g_nf[(size_t)NNODE * D];       // node features (out == h)
__device__ float g_agg[(size_t)NNODE * D];      // scatter-sum buffer
__device__ float g_deg[NNODE];                  // in-degree
__device__ float g_hx[NGRAPH * D];              // memory-LSTM hidden
// transposed weights: [c][row] layout for coalesced per-c access
__device__ float g_gwih_t[64 * 192];
__device__ float g_gwhh_t[64 * 192];
__device__ float g_swih_t[128 * 256];
__device__ float g_swhh_t[64 * 256];
__device__ float g_mwih_t[128 * 256];
__device__ float g_mwhh_t[64 * 256];
__device__ float g_l1t[320 * 64];

__device__ __forceinline__ float sigf(float x) { return 1.0f / (1.0f + expf(-x)); }

// ---------------- generic small transpose: dst[c*R + r] = src[r*C + c] ----------------
__global__ void k_tr(const float* __restrict__ src, float* __restrict__ dst, int R, int C) {
    int idx = blockIdx.x * blockDim.x + threadIdx.x;
    if (idx >= R * C) return;
    int r = idx / C, c = idx - r * C;
    dst[c * R + r] = src[idx];
}

// ---------------- lin0 + relu ----------------
__global__ void k_lin0(const float* __restrict__ x, const float* __restrict__ w,
                       const float* __restrict__ b) {
    int idx = blockIdx.x * blockDim.x + threadIdx.x;
    if (idx >= NNODE * D) return;
    int n = idx >> 6, j = idx & 63;
    float v = b[j];
    v = fmaf(x[n * 3 + 0], w[j * 3 + 0], v);
    v = fmaf(x[n * 3 + 1], w[j * 3 + 1], v);
    v = fmaf(x[n * 3 + 2], w[j * 3 + 2], v);
    g_nf[idx] = fmaxf(v, 0.0f);
}

// ---------------- edge hidden: relu(edge_attr @ e1_w^T + b) ----------------
__global__ void k_eh(const float* __restrict__ ea, const float* __restrict__ w,
                     const float* __restrict__ b) {
    int idx = blockIdx.x * blockDim.x + threadIdx.x;
    if (idx >= NEDGE * D) return;
    int e = idx >> 6, j = idx & 63;
    float acc = b[j];
#pragma unroll
    for (int c = 0; c < 6; c++) acc = fmaf(ea[e * 6 + c], w[j * 6 + c], acc);
    g_h1[idx] = fmaxf(acc, 0.0f);
}

// ---------------- degree ----------------
__global__ void k_zero_deg() {
    int i = blockIdx.x * blockDim.x + threadIdx.x;
    if (i < NNODE) g_deg[i] = 0.0f;
}
__global__ void k_deg(const int* __restrict__ ei) {
    int e = blockIdx.x * blockDim.x + threadIdx.x;
    if (e < NEDGE) atomicAdd(&g_deg[ei[NEDGE + e]], 1.0f);
}
__global__ void k_zero_agg() {
    int i = blockIdx.x * blockDim.x + threadIdx.x;
    if (i < NNODE * D) g_agg[i] = 0.0f;
}

// ---------------- ew GEMM: [E,64] @ e2_w^T[64,4096] + e2_b -> g_ewh (fp16) ----------------
// BM=128, BN=64, K=64, 256 threads, 8x4 register tile. As stored [k][m] (stride 129,
// conflict-free fill + broadcast reads), Bs [k][n] (stride 68, float4 reads conflict-free).
#define AS_S 129
#define BS_S 68
__global__ void k_gemm(const float* __restrict__ B, const float* __restrict__ bias) {
    __shared__ float As[64 * AS_S];
    __shared__ float Bs[64 * BS_S];
    int tid = threadIdx.x;
    int m0 = blockIdx.x * 128, n0 = blockIdx.y * 64;
#pragma unroll
    for (int i = 0; i < 8; i++) {
        int l = tid + i * 256;
        int m = l >> 4, k4 = (l & 15) << 2;
        float4 v = *(const float4*)(g_h1 + (size_t)(m0 + m) * 64 + k4);
        As[(k4 + 0) * AS_S + m] = v.x;
        As[(k4 + 1) * AS_S + m] = v.y;
        As[(k4 + 2) * AS_S + m] = v.z;
        As[(k4 + 3) * AS_S + m] = v.w;
    }
#pragma unroll
    for (int i = 0; i < 4; i++) {
        int l = tid + i * 256;
        int nn = l >> 4, k4 = (l & 15) << 2;
        float4 v = *(const float4*)(B + (size_t)(n0 + nn) * 64 + k4);
        Bs[(k4 + 0) * BS_S + nn] = v.x;
        Bs[(k4 + 1) * BS_S + nn] = v.y;
        Bs[(k4 + 2) * BS_S + nn] = v.z;
        Bs[(k4 + 3) * BS_S + nn] = v.w;
    }
    __syncthreads();
    int mb = (tid >> 4) * 8, nb = (tid & 15) * 4;
    float acc[8][4] = {};
#pragma unroll
    for (int k = 0; k < 64; k++) {
        float4 bv = *(const float4*)(&Bs[k * BS_S + nb]);
#pragma unroll
        for (int i = 0; i < 8; i++) {
            float a = As[k * AS_S + mb + i];
            acc[i][0] = fmaf(a, bv.x, acc[i][0]);
            acc[i][1] = fmaf(a, bv.y, acc[i][1]);
            acc[i][2] = fmaf(a, bv.z, acc[i][2]);
            acc[i][3] = fmaf(a, bv.w, acc[i][3]);
        }
    }
    float4 bb = *(const float4*)(bias + n0 + nb);
#pragma unroll
    for (int i = 0; i < 8; i++) {
        __half2 h01 = __floats2half2_rn(acc[i][0] + bb.x, acc[i][1] + bb.y);
        __half2 h23 = __floats2half2_rn(acc[i][2] + bb.z, acc[i][3] + bb.w);
        uint2 pk;
        pk.x = *(unsigned*)&h01;
        pk.y = *(unsigned*)&h23;
        *(uint2*)(g_ewh + (size_t)(m0 + mb + i) * 4096 + n0 + nb) = pk;
    }
}

// ---------------- message + scatter-add: msg_e = nf[src] @ ew_e ----------------
// one warp per edge, each lane computes 2 outputs via half2 loads (coalesced 128B/row)
__global__ void k_msg(const int* __restrict__ ei) {
    int le = threadIdx.x >> 5;
    int lane = threadIdx.x & 31;
    int e = blockIdx.x * 8 + le;
    __shared__ float s[8][64];
    int src = ei[e];
    *(float2*)&s[le][lane * 2] = *(const float2*)(g_nf + (size_t)src * 64 + lane * 2);
    __syncwarp();
    const __half2* w = (const __half2*)(g_ewh + (size_t)e * 4096) + lane;
    float acc0 = 0.0f, acc1 = 0.0f;
#pragma unroll 8
    for (int i = 0; i < 64; i++) {
        float2 wf = __half22float2(w[(size_t)i * 32]);
        float si = s[le][i];
        acc0 = fmaf(si, wf.x, acc0);
        acc1 = fmaf(si, wf.y, acc1);
    }
    int dst = ei[NEDGE + e];
    atomicAdd(&g_agg[(size_t)dst * 64 + lane * 2 + 0], acc0);
    atomicAdd(&g_agg[(size_t)dst * 64 + lane * 2 + 1], acc1);
}

// ---------------- conv-root + relu + GRU (fused, in-place on g_nf) ----------------
// 16 nodes per block; thread (li,j) handles j-th feature of 4 nodes -> weight loads
// amortized 4x, transposed GRU weights give coalesced per-c access.
__global__ void k_gru(const float* __restrict__ root_w, const float* __restrict__ conv_b,
                      const float* __restrict__ bih, const float* __restrict__ bhh) {
    int j = threadIdx.x & 63;
    int li = threadIdx.x >> 6;       // 0..3
    int nb = blockIdx.x * 16 + li * 4;
    __shared__ float sh[16][64];
    __shared__ float sm[16][64];
    float h[4];
#pragma unroll
    for (int p = 0; p < 4; p++) {
        h[p] = g_nf[(size_t)(nb + p) * 64 + j];
        sh[li * 4 + p][j] = h[p];
    }
    __syncthreads();
    float m[4];
#pragma unroll
    for (int p = 0; p < 4; p++)
        m[p] = g_agg[(size_t)(nb + p) * 64 + j] / fmaxf(g_deg[nb + p], 1.0f);
#pragma unroll 8
    for (int i = 0; i < 64; i++) {
        float w = root_w[i * 64 + j];
#pragma unroll
        for (int p = 0; p < 4; p++) m[p] = fmaf(sh[li * 4 + p][i], w, m[p]);
    }
    float cb = conv_b[j];
#pragma unroll
    for (int p = 0; p < 4; p++) {
        m[p] = fmaxf(m[p] + cb, 0.0f);
        sm[li * 4 + p][j] = m[p];
    }
    __syncthreads();
    float bi0 = bih[j], bi1 = bih[64 + j], bi2 = bih[128 + j];
    float bh0 = bhh[j], bh1 = bhh[64 + j], bh2 = bhh[128 + j];
    float gi0[4], gi1[4], gi2[4], gh0[4], gh1[4], gh2[4];
#pragma unroll
    for (int p = 0; p < 4; p++) {
        gi0[p] = bi0; gi1[p] = bi1; gi2[p] = bi2;
        gh0[p] = bh0; gh1[p] = bh1; gh2[p] = bh2;
    }
#pragma unroll 4
    for (int c = 0; c < 64; c++) {
        float wi0 = g_gwih_t[c * 192 + j];
        float wi1 = g_gwih_t[c * 192 + 64 + j];
        float wi2 = g_gwih_t[c * 192 + 128 + j];
        float wh0 = g_gwhh_t[c * 192 + j];
        float wh1 = g_gwhh_t[c * 192 + 64 + j];
        float wh2 = g_gwhh_t[c * 192 + 128 + j];
#pragma unroll
        for (int p = 0; p < 4; p++) {
            float mc = sm[li * 4 + p][c], hc = sh[li * 4 + p][c];
            gi0[p] = fmaf(mc, wi0, gi0[p]);
            gi1[p] = fmaf(mc, wi1, gi1[p]);
            gi2[p] = fmaf(mc, wi2, gi2[p]);
            gh0[p] = fmaf(hc, wh0, gh0[p]);
            gh1[p] = fmaf(hc, wh1, gh1[p]);
            gh2[p] = fmaf(hc, wh2, gh2[p]);
        }
    }
#pragma unroll
    for (int p = 0; p < 4; p++) {
        float r  = sigf(gi0[p] + gh0[p]);
        float z  = sigf(gi1[p] + gh1[p]);
        float nn = tanhf(gi2[p] + r * gh2[p]);
        g_nf[(size_t)(nb + p) * 64 + j] = (1.0f - z) * nn + z * h[p];
    }
}

// ---------------- Set2Set (6 steps) + memory LSTM, one block per graph ----------------
__global__ void k_s2s(const float* __restrict__ bih, const float* __restrict__ bhh,
                      const float* __restrict__ mbih, const float* __restrict__ mbhh,
                      float* d_hx_out, float* d_cx_out, int write_out) {
    int g = blockIdx.x, t = threadIdx.x;   // 128 threads
    __shared__ float so[64][65];
    __shared__ float hs[64], cs[64], q[128], gb[256], ab[64], red[64];
    for (int idx = t; idx < 4096; idx += 128)
        so[idx >> 6][idx & 63] = g_nf[(size_t)g * 4096 + idx];
    if (t < 64) { hs[t] = 0.0f; cs[t] = 0.0f; }
    q[t] = 0.0f;
    __syncthreads();
    for (int step = 0; step < 6; step++) {
        float a0 = bih[t] + bhh[t];
        float a1 = bih[128 + t] + bhh[128 + t];
#pragma unroll 8
        for (int c = 0; c < 128; c++) {
            float qc = q[c];
            a0 = fmaf(qc, g_swih_t[c * 256 + t], a0);
            a1 = fmaf(qc, g_swih_t[c * 256 + 128 + t], a1);
        }
#pragma unroll 8
        for (int c = 0; c < 64; c++) {
            float hc = hs[c];
            a0 = fmaf(hc, g_swhh_t[c * 256 + t], a0);
            a1 = fmaf(hc, g_swhh_t[c * 256 + 128 + t], a1);
        }
        gb[t] = a0; gb[128 + t] = a1;
        __syncthreads();
        if (t < 64) {
            float c = sigf(gb[64 + t]) * cs[t] + sigf(gb[t]) * tanhf(gb[128 + t]);
            cs[t] = c;
            hs[t] = sigf(gb[192 + t]) * tanhf(c);
        }
        __syncthreads();
        if (t < 64) {
            float acc = 0.0f;
#pragma unroll 8
            for (int dd = 0; dd < 64; dd++) acc = fmaf(so[t][dd], hs[dd], acc);
            ab[t] = acc; red[t] = acc;
        }
        __syncthreads();
        for (int s = 32; s > 0; s >>= 1) {
            if (t < s) red[t] = fmaxf(red[t], red[t + s]);
            __syncthreads();
        }
        float emax = red[0];
        __syncthreads();
        if (t < 64) { float a = expf(ab[t] - emax); ab[t] = a; red[t] = a; }
        __syncthreads();
        for (int s = 32; s > 0; s >>= 1) {
            if (t < s) red[t] += red[t + s];
            __syncthreads();
        }
        float asum = red[0];
        __syncthreads();
        if (t < 64) {
            float acc = 0.0f;
#pragma unroll 8
            for (int n2 = 0; n2 < 64; n2++) acc = fmaf(ab[n2], so[n2][t], acc);
            q[t] = hs[t];
            q[64 + t] = acc / asum;
        }
        __syncthreads();
    }
    // memory LSTM from zero state
    {
        float a0 = mbih[t] + mbhh[t];
        float a1 = mbih[128 + t] + mbhh[128 + t];
#pragma unroll 8
        for (int c = 0; c < 128; c++) {
            float qc = q[c];
            a0 = fmaf(qc, g_mwih_t[c * 256 + t], a0);
            a1 = fmaf(qc, g_mwih_t[c * 256 + 128 + t], a1);
        }
        gb[t] = a0; gb[128 + t] = a1;
    }
    __syncthreads();
    if (t < 64) {
        float c  = sigf(gb[t]) * tanhf(gb[128 + t]);   // f*0 + i*tanh(g)
        float hx = sigf(gb[192 + t]) * tanhf(c);
        g_hx[g * 64 + t] = hx;
        if (write_out) { d_hx_out[g * 64 + t] = hx; d_cx_out[g * 64 + t] = c; }
    }
}

// ---------------- head: faithful view(4,-1,d)+transpose(2,1,0) feat -> lin1 -> lin2 ----------------
__global__ void k_final(const int* __restrict__ nonring, const int* __restrict__ nrbidx,
                        const float* __restrict__ b1,
                        const float* __restrict__ w2, const float* __restrict__ b2,
                        float* __restrict__ outp) {
    int r = blockIdx.x, t = threadIdx.x;   // 128 threads
    __shared__ float feat[320];
    __shared__ float o1[64];
    for (int c = t; c < 320; c += 128) {
        int flat = r * 320 + c;
        int i0 = flat / 15360;            // dim index (0..63)
        int rem = flat - i0 * 15360;
        int i1 = rem / 5;                 // torsion index
        int i2 = rem - i1 * 5;            // which of [lstm, n0..n3]
        float v;
        if (i2 == 0) v = g_hx[nrbidx[i1] * 64 + i0];
        else {
            int node = nonring[(i2 - 1) * NTORS + i1];
            v = g_nf[(size_t)node * 64 + i0];
        }
        feat[c] = v;
    }
    __syncthreads();
    if (t < 64) {
        float acc = b1[t];
#pragma unroll 8
        for (int c = 0; c < 320; c++) acc = fmaf(feat[c], g_l1t[c * 64 + t], acc);
        o1[t] = fmaxf(acc, 0.0f);
    }
    __syncthreads();
    if (t < 6) {
        float acc = b2[t];
        const float* wr = w2 + (size_t)t * 64;
#pragma unroll
        for (int c = 0; c < 64; c++) acc = fmaf(o1[c], wr[c], acc);
        outp[r * 6 + t] = acc;
    }
}

// ---------------- launch ----------------
extern "C" void kernel_launch(void* const* d_in, const int* in_sizes, int n_in,
                              void* d_out, int out_size) {
    const float* x       = (const float*)d_in[0];
    const float* ea      = (const float*)d_in[1];
    const int*   ei      = (const int*)d_in[2];
    const int*   nonring = (const int*)d_in[4];
    const int*   nrbidx  = (const int*)d_in[5];
    int base = n_in - 24;
    const float* lin0_w  = (const float*)d_in[base + 0];
    const float* lin0_b  = (const float*)d_in[base + 1];
    const float* e1_w    = (const float*)d_in[base + 2];
    const float* e1_b    = (const float*)d_in[base + 3];
    const float* e2_w    = (const float*)d_in[base + 4];
    const float* e2_b    = (const float*)d_in[base + 5];
    const float* root_w  = (const float*)d_in[base + 6];
    const float* conv_b  = (const float*)d_in[base + 7];
    const float* gru_wih = (const float*)d_in[base + 8];
    const float* gru_whh = (const float*)d_in[base + 9];
    const float* gru_bih = (const float*)d_in[base + 10];
    const float* gru_bhh = (const float*)d_in[base + 11];
    const float* s2s_wih = (const float*)d_in[base + 12];
    const float* s2s_whh = (const float*)d_in[base + 13];
    const float* s2s_bih = (const float*)d_in[base + 14];
    const float* s2s_bhh = (const float*)d_in[base + 15];
    const float* mem_wih = (const float*)d_in[base + 16];
    const float* mem_whh = (const float*)d_in[base + 17];
    const float* mem_bih = (const float*)d_in[base + 18];
    const float* mem_bhh = (const float*)d_in[base + 19];
    const float* lin1_w  = (const float*)d_in[base + 20];
    const float* lin1_b  = (const float*)d_in[base + 21];
    const float* lin2_w  = (const float*)d_in[base + 22];
    const float* lin2_b  = (const float*)d_in[base + 23];
    float* outp = (float*)d_out;

    // resolve transposed-weight scratch pointers
    float *p_gwih, *p_gwhh, *p_swih, *p_swhh, *p_mwih, *p_mwhh, *p_l1t;
    cudaGetSymbolAddress((void**)&p_gwih, g_gwih_t);
    cudaGetSymbolAddress((void**)&p_gwhh, g_gwhh_t);
    cudaGetSymbolAddress((void**)&p_swih, g_swih_t);
    cudaGetSymbolAddress((void**)&p_swhh, g_swhh_t);
    cudaGetSymbolAddress((void**)&p_mwih, g_mwih_t);
    cudaGetSymbolAddress((void**)&p_mwhh, g_mwhh_t);
    cudaGetSymbolAddress((void**)&p_l1t,  g_l1t);

    k_tr<<<(192 * 64 + 255) / 256, 256>>>(gru_wih, p_gwih, 192, 64);
    k_tr<<<(192 * 64 + 255) / 256, 256>>>(gru_whh, p_gwhh, 192, 64);
    k_tr<<<(256 * 128 + 255) / 256, 256>>>(s2s_wih, p_swih, 256, 128);
    k_tr<<<(256 * 64 + 255) / 256, 256>>>(s2s_whh, p_swhh, 256, 64);
    k_tr<<<(256 * 128 + 255) / 256, 256>>>(mem_wih, p_mwih, 256, 128);
    k_tr<<<(256 * 64 + 255) / 256, 256>>>(mem_whh, p_mwhh, 256, 64);
    k_tr<<<(64 * 320 + 255) / 256, 256>>>(lin1_w, p_l1t, 64, 320);

    k_lin0<<<(NNODE * D) / 256, 256>>>(x, lin0_w, lin0_b);
    k_eh<<<(NEDGE * D) / 256, 256>>>(ea, e1_w, e1_b);
    k_zero_deg<<<NNODE / 256, 256>>>();
    k_deg<<<NEDGE / 256, 256>>>(ei);
    k_gemm<<<dim3(NEDGE / 128, 4096 / 64), 256>>>(e2_w, e2_b);

    for (int it = 0; it < 6; it++) {
        k_zero_agg<<<(NNODE * D) / 256, 256>>>();
        k_msg<<<NEDGE / 8, 256>>>(ei);
        k_gru<<<NNODE / 16, 256>>>(root_w, conv_b, gru_bih, gru_bhh);
    }

    int wout = (out_size >= 51200) ? 1 : 0;
    k_s2s<<<NGRAPH, 128>>>(s2s_bih, s2s_bhh, mem_bih, mem_bhh,
                           outp + 18432, outp + 18432 + 16384, wout);
    k_final<<<NTORS, 128>>>(nonring, nrbidx, lin1_b, lin2_w, lin2_b, outp);
}